// round 2
// baseline (speedup 1.0000x reference)
#include <cuda_runtime.h>
#include <cstdint>
#include <math.h>

// Problem constants
#define NUM_CLASSES 80
#define H 256
#define W 256
#define HW 65536          // H*W
#define TOPK 100
#define CAND_CAP (NUM_CLASSES * HW)   // worst case: every position is a peak
#define FINAL_CAP 2048

// ---------------- device scratch (static: no allocation allowed) ----------------
__device__ unsigned long long g_cands[CAND_CAP];   // 42 MB
__device__ unsigned int       g_hist[65536];
__device__ unsigned int       g_counter;
__device__ unsigned int       g_nfinal;
__device__ unsigned int       g_threshold;
__device__ unsigned long long g_final[FINAL_CAP];

__device__ __forceinline__ float sigm(float x) {
    return 1.0f / (1.0f + __expf(-x));
}
// High-accuracy sigmoid (double internally, rounded to fp32) for tie decisions.
__device__ __forceinline__ float sigm_acc(float x) {
    return (float)(1.0 / (1.0 + exp(-(double)x)));
}

// ---------------- kernel 1: zero counters/histogram (graph-replay safe) ----------------
__global__ void initKernel() {
    int i = blockIdx.x * blockDim.x + threadIdx.x;
    if (i < 65536) g_hist[i] = 0u;
    if (i == 0) { g_counter = 0u; g_nfinal = 0u; g_threshold = 0u; }
}

// ---------------- kernel 2: peak detection + candidate compaction ----------------
// One block = one 32x32 tile of one class (batch 0 only). 5x5 maxpool done in
// LOGIT space (sigmoid is monotone), sigmoid evaluated only for kept peaks and
// the rare near-tie path (reproduces reference's sigmoid-space equality).
__global__ __launch_bounds__(1024, 2) void peakKernel(const float* __restrict__ cls) {
    __shared__ float sT[36 * 36];   // logit tile with 2-halo
    __shared__ float sH[36 * 32];   // horizontal 5-max
    __shared__ unsigned sWarpBase[32];
    __shared__ unsigned sCnt;
    __shared__ unsigned sBlockBase;

    const int blk  = blockIdx.x;
    const int c    = blk >> 6;          // class
    const int tile = blk & 63;          // 8x8 tiles of 32x32
    const int ty0  = (tile >> 3) << 5;
    const int tx0  = (tile & 7)  << 5;
    const float* base = cls + (size_t)c * HW;   // batch 0

    const int t = threadIdx.x;
    if (t == 0) sCnt = 0u;

    // load 36x36 halo tile (OOB -> very negative)
    for (int i = t; i < 36 * 36; i += 1024) {
        int r  = i / 36, col = i - r * 36;
        int gr = ty0 + r - 2, gc = tx0 + col - 2;
        float v = -1e30f;
        if ((unsigned)gr < 256u && (unsigned)gc < 256u)
            v = __ldg(&base[(gr << 8) + gc]);
        sT[i] = v;
    }
    __syncthreads();

    // horizontal 5-max: rows 0..35, output cols 0..31
    for (int i = t; i < 36 * 32; i += 1024) {
        int r = i >> 5, cc = i & 31;
        const float* p = &sT[r * 36 + cc];
        sH[i] = fmaxf(fmaxf(fmaxf(p[0], p[1]), fmaxf(p[2], p[3])), p[4]);
    }
    __syncthreads();

    // vertical 5-max: one output per thread
    const int r  = t >> 5;
    const int cc = t & 31;
    float m = sH[r * 32 + cc];
    m = fmaxf(m, sH[(r + 1) * 32 + cc]);
    m = fmaxf(m, sH[(r + 2) * 32 + cc]);
    m = fmaxf(m, sH[(r + 3) * 32 + cc]);
    m = fmaxf(m, sH[(r + 4) * 32 + cc]);
    const float x = sT[(r + 2) * 36 + (cc + 2)];

    bool keep = (m == x);
    float score = 0.0f;
    if (keep) {
        score = sigm(x);
    } else if (m - x < 1e-3f) {
        // reference keeps if sigmoid(max)==sigmoid(center) even when logits differ
        float sm = sigm_acc(m), sx = sigm_acc(x);
        if (__float_as_uint(sm) == __float_as_uint(sx)) { keep = true; score = sx; }
    }

    unsigned long long key = 0ULL;
    if (keep) {
        unsigned hw  = (unsigned)(((ty0 + r) << 8) + tx0 + cc);
        unsigned idx = ((unsigned)c << 16) | hw;
        unsigned sb  = __float_as_uint(score);           // score > 0 -> monotone bits
        key = ((unsigned long long)sb << 32) | (0xFFFFFFFFu - idx);
        atomicAdd(&g_hist[sb >> 16], 1u);
    }

    // block-level stream compaction
    const unsigned mask = __ballot_sync(0xFFFFFFFFu, keep);
    const int lane = t & 31, wid = t >> 5;
    if (lane == 0) sWarpBase[wid] = atomicAdd(&sCnt, (unsigned)__popc(mask));
    __syncthreads();
    if (t == 0) sBlockBase = atomicAdd(&g_counter, sCnt);
    __syncthreads();
    if (keep) {
        unsigned pos = sBlockBase + sWarpBase[wid] + (unsigned)__popc(mask & ((1u << lane) - 1u));
        g_cands[pos] = key;
    }
}

// ---------------- kernel 3: find score-bin threshold of the 100th candidate ----------------
__global__ void thresholdKernel() {
    __shared__ unsigned sa[1024], sb[1024];
    const int t = threadIdx.x;
    const int base = t * 64;
    unsigned sum = 0;
    #pragma unroll 8
    for (int i = 0; i < 64; i++) sum += g_hist[base + i];
    sa[t] = sum;
    __syncthreads();
    unsigned* src = sa; unsigned* dst = sb;
    for (int off = 1; off < 1024; off <<= 1) {
        unsigned v = src[t];
        if (t + off < 1024) v += src[t + off];
        dst[t] = v;
        __syncthreads();
        unsigned* tmp = src; src = dst; dst = tmp;
    }
    // src[t] = suffix count (non-increasing in t)
    if (src[0] < TOPK) { if (t == 0) g_threshold = 0u; return; }
    unsigned mine = src[t];
    unsigned next = (t < 1023) ? src[t + 1] : 0u;
    if (mine >= TOPK && next < TOPK) {
        unsigned running = next;
        unsigned T = (unsigned)base;
        for (int b = base + 63; b >= base; b--) {
            running += g_hist[b];
            if (running >= TOPK) { T = (unsigned)b; break; }
        }
        g_threshold = T;
    }
}

// ---------------- kernel 4: filter candidates >= threshold bin ----------------
__global__ void filterKernel() {
    const unsigned N = g_counter;
    const unsigned T = g_threshold;
    const unsigned stride = gridDim.x * blockDim.x;
    for (unsigned i = blockIdx.x * blockDim.x + threadIdx.x; i < N; i += stride) {
        unsigned long long k = g_cands[i];
        if ((unsigned)(k >> 48) >= T) {
            unsigned p = atomicAdd(&g_nfinal, 1u);
            if (p < FINAL_CAP) g_final[p] = k;
        }
    }
}

// ---------------- kernel 5: sort finalists, decode top-100, pad output ----------------
__global__ void emitKernel(const float* __restrict__ txty, float* __restrict__ out,
                           int out_size) {
    __shared__ unsigned long long keys[FINAL_CAP];
    const int t = threadIdx.x;
    unsigned M = g_nfinal;
    if (M > FINAL_CAP) M = FINAL_CAP;
    for (int i = t; i < FINAL_CAP; i += 1024)
        keys[i] = (i < (int)M) ? g_final[i] : 0ULL;
    __syncthreads();

    // bitonic sort, descending
    for (int k = 2; k <= FINAL_CAP; k <<= 1) {
        for (int j = k >> 1; j > 0; j >>= 1) {
            for (int i = t; i < FINAL_CAP; i += 1024) {
                int ixj = i ^ j;
                if (ixj > i) {
                    unsigned long long A = keys[i], B = keys[ixj];
                    bool desc = ((i & k) == 0);
                    if (desc ? (A < B) : (A > B)) { keys[i] = B; keys[ixj] = A; }
                }
            }
            __syncthreads();
        }
    }

    if (t < TOPK) {
        unsigned long long key = keys[t];
        float score  = __uint_as_float((unsigned)(key >> 32));
        unsigned idx = 0xFFFFFFFFu - (unsigned)(key & 0xFFFFFFFFu);
        unsigned cls = idx >> 16;
        unsigned hw  = idx & 0xFFFFu;
        unsigned gy  = hw >> 8, gx = hw & 0xFFu;
        float tx = __ldg(&txty[hw]);           // txty_pred[0, 0, gy, gx]
        float ty = __ldg(&txty[HW + hw]);      // txty_pred[0, 1, gy, gx]
        float bx = (sigm(tx) + (float)gx) * (4.0f / 1024.0f);
        float by = (sigm(ty) + (float)gy) * (4.0f / 1024.0f);
        bx = fminf(fmaxf(bx, 0.0f), 1.0f);
        by = fminf(fmaxf(by, 0.0f), 1.0f);
        out[t * 4 + 0] = bx;
        out[t * 4 + 1] = by;
        out[t * 4 + 2] = 0.0f;
        out[t * 4 + 3] = 0.0f;
        out[400 + t] = score;
        out[500 + t] = (float)cls;
    }
    // zero any padding beyond the 600 payload elements (out is poisoned 0xAA)
    for (int i = 600 + t; i < out_size; i += 1024) out[i] = 0.0f;
}

// ---------------- launch ----------------
extern "C" void kernel_launch(void* const* d_in, const int* in_sizes, int n_in,
                              void* d_out, int out_size) {
    const float* cls  = (const float*)d_in[0];   // (8, 80, 256, 256) fp32
    const float* txty = (const float*)d_in[1];   // (8, 2, 256, 256) fp32
    float* out = (float*)d_out;                  // 400 bbox + 100 score + 100 class

    initKernel<<<64, 1024>>>();
    peakKernel<<<NUM_CLASSES * 64, 1024>>>(cls);
    thresholdKernel<<<1, 1024>>>();
    filterKernel<<<256, 256>>>();
    emitKernel<<<1, 1024>>>(txty, out, out_size);
}

// round 3
// speedup vs baseline: 1.3222x; 1.3222x over previous
#include <cuda_runtime.h>
#include <cstdint>
#include <math.h>

#define NUM_CLASSES 80
#define H 256
#define W 256
#define HW 65536
#define TOPK 100
#define CAND_CAP (NUM_CLASSES * HW)
#define FINAL_CAP 2048
#define SROW 264                     // padded sT row stride (floats)
#define STAGE_CAP 2048               // per-block smem candidate staging

// ---------------- device scratch ----------------
__device__ unsigned long long g_cands[CAND_CAP];
__device__ unsigned int       g_hist[65536];
__device__ unsigned int       g_partial[1024];
__device__ unsigned int       g_counter;
__device__ unsigned int       g_nfinal;
__device__ unsigned int       g_threshold;
__device__ unsigned long long g_final[FINAL_CAP];

__device__ __forceinline__ float sigm(float x) {
    return 1.0f / (1.0f + __expf(-x));
}
__device__ __forceinline__ float sigm_acc(float x) {
    return (float)(1.0 / (1.0 + exp(-(double)x)));
}

// ---------------- kernel 1: init ----------------
__global__ void initKernel() {
    int i = blockIdx.x * blockDim.x + threadIdx.x;   // 16384 threads
    ((uint4*)g_hist)[i] = make_uint4(0u, 0u, 0u, 0u);
    if (i == 0) { g_counter = 0u; g_nfinal = 0u; g_threshold = 0u; }
}

// ---------------- kernel 2: peak detect, 32x256 strips ----------------
// grid = 80 classes * 8 strips, 512 threads. 5x5 maxpool in logit space
// (sigmoid monotone); sigmoid only for peaks / near-ties.
__global__ __launch_bounds__(512, 2) void peakKernel(const float* __restrict__ cls) {
    extern __shared__ float smem[];
    float* sT = smem;                              // 36 x SROW
    float* sH = smem + 36 * SROW;                  // 36 x 256
    unsigned long long* sKeys =
        (unsigned long long*)(sH + 36 * 256);      // STAGE_CAP
    __shared__ unsigned sCnt, sBase;

    const int c    = blockIdx.x >> 3;
    const int row0 = (blockIdx.x & 7) << 5;
    const float* base = cls + (size_t)c * HW;      // batch 0
    const int t = threadIdx.x;
    if (t == 0) sCnt = 0u;

    // column pads (-inf) at sT cols 2,3,260,261 for each of 36 rows
    if (t < 144) {
        int r = t >> 2, p = t & 3;
        int col = (p < 2) ? (2 + p) : (258 + p);
        sT[r * SROW + col] = -1e30f;
    }
    // load 36 rows x 256 cols, float4-coalesced (rows row0-2 .. row0+33)
    for (int i = t; i < 36 * 64; i += 512) {
        int r = i >> 6, q = i & 63;
        int gr = row0 + r - 2;
        float4 v;
        if ((unsigned)gr < 256u)
            v = __ldg((const float4*)(base + (gr << 8)) + q);
        else
            v = make_float4(-1e30f, -1e30f, -1e30f, -1e30f);
        *(float4*)&sT[r * SROW + 4 + (q << 2)] = v;
    }
    __syncthreads();

    // horizontal 5-max over 36 rows
    for (int i = t; i < 36 * 256; i += 512) {
        int r = i >> 8, cc = i & 255;
        const float* p = &sT[r * SROW + 2 + cc];
        sH[i] = fmaxf(fmaxf(fmaxf(p[0], p[1]), fmaxf(p[2], p[3])), p[4]);
    }
    __syncthreads();

    const int lane = t & 31;
    const unsigned lt = (1u << lane) - 1u;

    // vertical 5-max + candidate emit, 16 outputs/thread
    #pragma unroll 4
    for (int it = 0; it < 16; it++) {
        int o  = it * 512 + t;
        int r  = o >> 8, cc = o & 255;
        float m = sH[r * 256 + cc];
        m = fmaxf(m, sH[(r + 1) * 256 + cc]);
        m = fmaxf(m, sH[(r + 2) * 256 + cc]);
        m = fmaxf(m, sH[(r + 3) * 256 + cc]);
        m = fmaxf(m, sH[(r + 4) * 256 + cc]);
        float x = sT[(r + 2) * SROW + 4 + cc];

        bool keep = (m == x);
        float score = 0.0f;
        if (keep) {
            score = sigm(x);
        } else if (m - x < 1e-3f) {
            float sm = sigm_acc(m), sx = sigm_acc(x);
            if (__float_as_uint(sm) == __float_as_uint(sx)) { keep = true; score = sx; }
        }

        unsigned mball = __ballot_sync(0xFFFFFFFFu, keep);
        if (mball) {
            unsigned wbase = 0;
            if (lane == 0) wbase = atomicAdd(&sCnt, (unsigned)__popc(mball));
            wbase = __shfl_sync(0xFFFFFFFFu, wbase, 0);
            if (keep) {
                unsigned hw  = (unsigned)(((row0 + r) << 8) | cc);
                unsigned idx = ((unsigned)c << 16) | hw;
                unsigned sb  = __float_as_uint(score);
                unsigned long long key =
                    ((unsigned long long)sb << 32) | (0xFFFFFFFFu - idx);
                unsigned pos = wbase + (unsigned)__popc(mball & lt);
                if (pos < STAGE_CAP) {
                    sKeys[pos] = key;
                } else {                      // pathological overflow spill
                    unsigned g = atomicAdd(&g_counter, 1u);
                    g_cands[g] = key;
                }
                atomicAdd(&g_hist[sb >> 16], 1u);
            }
        }
    }
    __syncthreads();

    unsigned M = sCnt; if (M > STAGE_CAP) M = STAGE_CAP;
    if (t == 0) sBase = atomicAdd(&g_counter, M);
    __syncthreads();
    for (unsigned i = t; i < M; i += 512) g_cands[sBase + i] = sKeys[i];
}

// ---------------- kernel 3: 1024 partial sums of 64-bin chunks ----------------
__global__ void partialKernel() {           // 64 blocks x 512 (16 warps)
    int j    = blockIdx.x * 16 + (threadIdx.x >> 5);
    int lane = threadIdx.x & 31;
    unsigned s = g_hist[j * 64 + lane] + g_hist[j * 64 + 32 + lane];
    #pragma unroll
    for (int o = 16; o; o >>= 1) s += __shfl_down_sync(0xFFFFFFFFu, s, o);
    if (lane == 0) g_partial[j] = s;
}

// ---------------- kernel 4: threshold bin of the 100th candidate ----------------
__global__ void thresholdKernel() {
    __shared__ unsigned sa[1024], sb[1024];
    __shared__ unsigned sChunk, sAbove, sFine[64];
    const int t = threadIdx.x;
    sa[t] = g_partial[t];
    __syncthreads();
    unsigned* src = sa; unsigned* dst = sb;
    for (int off = 1; off < 1024; off <<= 1) {
        unsigned v = src[t];
        if (t + off < 1024) v += src[t + off];
        dst[t] = v;
        __syncthreads();
        unsigned* tmp = src; src = dst; dst = tmp;
    }
    if (src[0] < TOPK) { if (t == 0) g_threshold = 0u; return; }
    unsigned mine = src[t];
    unsigned next = (t < 1023) ? src[t + 1] : 0u;
    if (mine >= TOPK && next < TOPK) { sChunk = (unsigned)t; sAbove = next; }
    __syncthreads();
    const unsigned jc = sChunk, above = sAbove;
    if (t < 64) {
        unsigned s = above;
        for (int b = t; b < 64; b++) s += g_hist[jc * 64 + b];
        sFine[t] = s;
    }
    __syncthreads();
    if (t < 64) {
        unsigned s = sFine[t];
        unsigned nx = (t < 63) ? sFine[t + 1] : above;
        if (s >= TOPK && nx < TOPK) g_threshold = jc * 64 + (unsigned)t;
    }
}

// ---------------- kernel 5: filter ----------------
__global__ void filterKernel() {
    const unsigned N = g_counter;
    const unsigned T = g_threshold;
    const unsigned stride = gridDim.x * blockDim.x;
    for (unsigned i = blockIdx.x * blockDim.x + threadIdx.x; i < N; i += stride) {
        unsigned long long k = g_cands[i];
        if ((unsigned)(k >> 48) >= T) {
            unsigned p = atomicAdd(&g_nfinal, 1u);
            if (p < FINAL_CAP) g_final[p] = k;
        }
    }
}

// ---------------- kernel 6: sort finalists (dynamic size), decode top-100 ----------------
__global__ void emitKernel(const float* __restrict__ txty, float* __restrict__ out,
                           int out_size) {
    __shared__ unsigned long long keys[FINAL_CAP];
    const int t = threadIdx.x;
    unsigned M = g_nfinal;
    if (M > FINAL_CAP) M = FINAL_CAP;
    int P = 256; while (P < (int)M) P <<= 1;

    for (int i = t; i < P; i += 1024)
        keys[i] = (i < (int)M) ? g_final[i] : 0ULL;
    __syncthreads();

    for (int k = 2; k <= P; k <<= 1) {
        for (int j = k >> 1; j > 0; j >>= 1) {
            for (int i = t; i < P; i += 1024) {
                int ixj = i ^ j;
                if (ixj > i) {
                    unsigned long long A = keys[i], B = keys[ixj];
                    bool desc = ((i & k) == 0);
                    if (desc ? (A < B) : (A > B)) { keys[i] = B; keys[ixj] = A; }
                }
            }
            __syncthreads();
        }
    }

    if (t < TOPK) {
        unsigned long long key = keys[t];
        float score  = __uint_as_float((unsigned)(key >> 32));
        unsigned idx = 0xFFFFFFFFu - (unsigned)(key & 0xFFFFFFFFu);
        unsigned cls = idx >> 16;
        unsigned hw  = idx & 0xFFFFu;
        unsigned gy  = hw >> 8, gx = hw & 0xFFu;
        float tx = __ldg(&txty[hw]);
        float ty = __ldg(&txty[HW + hw]);
        float bx = (sigm(tx) + (float)gx) * (4.0f / 1024.0f);
        float by = (sigm(ty) + (float)gy) * (4.0f / 1024.0f);
        bx = fminf(fmaxf(bx, 0.0f), 1.0f);
        by = fminf(fmaxf(by, 0.0f), 1.0f);
        out[t * 4 + 0] = bx;
        out[t * 4 + 1] = by;
        out[t * 4 + 2] = 0.0f;
        out[t * 4 + 3] = 0.0f;
        out[400 + t] = score;
        out[500 + t] = (float)cls;
    }
    for (int i = 600 + t; i < out_size; i += 1024) out[i] = 0.0f;
}

// ---------------- launch ----------------
extern "C" void kernel_launch(void* const* d_in, const int* in_sizes, int n_in,
                              void* d_out, int out_size) {
    const float* cls  = (const float*)d_in[0];
    const float* txty = (const float*)d_in[1];
    float* out = (float*)d_out;

    const int peakSmem = (36 * SROW + 36 * 256) * 4 + STAGE_CAP * 8;  // 91,264 B
    static bool attrSet = false;
    if (!attrSet) {
        cudaFuncSetAttribute(peakKernel,
                             cudaFuncAttributeMaxDynamicSharedMemorySize, peakSmem);
        attrSet = true;
    }

    initKernel<<<64, 256>>>();
    peakKernel<<<NUM_CLASSES * 8, 512, peakSmem>>>(cls);
    partialKernel<<<64, 512>>>();
    thresholdKernel<<<1, 1024>>>();
    filterKernel<<<1024, 256>>>();
    emitKernel<<<1, 1024>>>(txty, out, out_size);
}